// round 16
// baseline (speedup 1.0000x reference)
#include <cuda_runtime.h>
#include <cuda_fp16.h>
#include <cstdint>

#define N_C   100000
#define N_PC  10000
#define NE    1000000
#define D     128
#define NL    3
#define KCOMB 384
#define LN_EPS 1e-5f
#define NCHUNK 98          // ceil(N_C/1024)
#define TS 40              // fp16 elems per smem tile row (32 + 8 pad)
#define NC4  (N_C * D / 4)
#define NPC4 (N_PC * D / 4)

// ---------------- device scratch (static, no allocation) ----------------
static __device__ __align__(16) __half g_h16[N_C * D];
static __device__ __align__(16) __half g_pc16[N_PC * D];
static __device__ __align__(16) __half g_m16[2][N_C * D];
static __device__ __align__(16) __half g_w16[NL * D * KCOMB];   // [l][n][k]
static __device__ __align__(16) __half g_lw16[NL * D * D];      // [l][n][k]
static __device__ int   g_deg[2][N_C];
static __device__ int   g_off[2][N_C + 1];
static __device__ int   g_cur[2][N_C];
static __device__ int   g_esrc[2][NE];
static __device__ int   g_psum[2][NCHUNK + 1];
static __device__ float g_bcomb[NL][D];

// ---------------- input conversion fp32 -> fp16 (both tensors) ----------
__global__ void cvt_all(const float4* __restrict__ xc, const float4* __restrict__ xpc,
                        uint2* __restrict__ yc, uint2* __restrict__ ypc) {
    int i = blockIdx.x * blockDim.x + threadIdx.x;
    if (i < NC4) {
        float4 v = xc[i];
        __half2 lo = __floats2half2_rn(v.x, v.y);
        __half2 hi = __floats2half2_rn(v.z, v.w);
        yc[i] = make_uint2(*(uint32_t*)&lo, *(uint32_t*)&hi);
    } else if (i < NC4 + NPC4) {
        float4 v = xpc[i - NC4];
        __half2 lo = __floats2half2_rn(v.x, v.y);
        __half2 hi = __floats2half2_rn(v.z, v.w);
        ypc[i - NC4] = make_uint2(*(uint32_t*)&lo, *(uint32_t*)&hi);
    }
}

// ---------------- weight prep (combined, transposed, fp16) --------------
__global__ void prep_weights(const float* __restrict__ Wself,
                             const float* __restrict__ Wneigh,
                             const float* __restrict__ bneigh,
                             const float* __restrict__ linW) {
    int idx = blockIdx.x * blockDim.x + threadIdx.x;
    int total = NL * KCOMB * D;
    if (idx < total) {
        int l = idx / (KCOMB * D);
        int rem = idx - l * (KCOMB * D);
        int k = rem / D;
        int n = rem - k * D;
        float v;
        if (k < D) {
            v = Wself[((l * 2 + 0) * D + k) * D + n] +
                Wself[((l * 2 + 1) * D + k) * D + n];
        } else if (k < 2 * D) {
            v = Wneigh[((l * 2 + 0) * D + (k - D)) * D + n];
        } else {
            v = Wneigh[((l * 2 + 1) * D + (k - 2 * D)) * D + n];
        }
        g_w16[(l * D + n) * KCOMB + k] = __float2half_rn(v);
    }
    if (idx < NL * D * D) {
        int l = idx / (D * D);
        int rem = idx - l * (D * D);
        int k = rem / D;
        int n = rem - k * D;
        g_lw16[(l * D + n) * D + k] = __float2half_rn(linW[idx]);
    }
    if (idx < NL * D) {
        int l = idx / D, n = idx - l * D;
        g_bcomb[l][n] = bneigh[(l * 2 + 0) * D + n] + bneigh[(l * 2 + 1) * D + n];
    }
}

// ---------------- CSR build --------------------------------------------
__global__ void hist_kernel(const int* __restrict__ dst0,
                            const int* __restrict__ dst1) {
    int idx = blockIdx.x * blockDim.x + threadIdx.x;
    if (idx < NE) {
        atomicAdd(&g_deg[0][dst0[idx]], 1);
    } else if (idx < 2 * NE) {
        atomicAdd(&g_deg[1][dst1[idx - NE]], 1);
    }
}

__global__ void scan_partial() {
    int r = blockIdx.y;
    int i = blockIdx.x * 1024 + threadIdx.x;
    int lane = threadIdx.x & 31, wid = threadIdx.x >> 5;
    int v = (i < N_C) ? g_deg[r][i] : 0;
    int x = v;
#pragma unroll
    for (int o = 1; o < 32; o <<= 1) {
        int y = __shfl_up_sync(0xffffffffu, x, o);
        if (lane >= o) x += y;
    }
    __shared__ int ws[32];
    if (lane == 31) ws[wid] = x;
    __syncthreads();
    if (wid == 0) {
        int y = ws[lane];
#pragma unroll
        for (int o = 1; o < 32; o <<= 1) {
            int z = __shfl_up_sync(0xffffffffu, y, o);
            if (lane >= o) y += z;
        }
        ws[lane] = y;
    }
    __syncthreads();
    int base = wid ? ws[wid - 1] : 0;
    if (i < N_C) g_off[r][i] = base + x - v;
    if (threadIdx.x == 1023) g_psum[r][blockIdx.x] = base + x;
}

// add_base with in-block parallel reduction of chunk totals
__global__ void add_base2() {
    int r = blockIdx.y;
    __shared__ int sarr[128];
    int tid = threadIdx.x;
    if (tid < 128) sarr[tid] = (tid < blockIdx.x && tid < NCHUNK) ? g_psum[r][tid] : 0;
    __syncthreads();
#pragma unroll
    for (int o = 64; o; o >>= 1) {
        if (tid < o) sarr[tid] += sarr[tid + o];
        __syncthreads();
    }
    int base = sarr[0];
    int i = blockIdx.x * 1024 + tid;
    if (i < N_C) {
        int o = g_off[r][i] + base;
        g_off[r][i] = o;
        g_cur[r][i] = o;
    }
    if (tid == 0 && blockIdx.x == NCHUNK - 1)
        g_off[r][N_C] = base + g_psum[r][NCHUNK - 1];
}

__global__ void scatter_kernel(const int* __restrict__ src0,
                               const int* __restrict__ dst0,
                               const int* __restrict__ src1,
                               const int* __restrict__ dst1) {
    int idx = blockIdx.x * blockDim.x + threadIdx.x;
    if (idx < NE) {
        int d = dst0[idx];
        int p = atomicAdd(&g_cur[0][d], 1);
        g_esrc[0][p] = src0[idx];
    } else if (idx < 2 * NE) {
        int e = idx - NE;
        int d = dst1[e];
        int p = atomicAdd(&g_cur[1][d], 1);
        g_esrc[1][p] = src1[e];
    }
}

// ------ mean aggregation: warp/dst, 4-deep prefetch; 64-thread blocks ---
__global__ void agg_kernel(const __half* __restrict__ h) {
    int rel = blockIdx.y;
    int gw = (blockIdx.x * blockDim.x + threadIdx.x) >> 5;
    int lane = threadIdx.x & 31;
    if (gw >= N_C) return;
    __half* __restrict__ out = g_m16[rel];
    const int* __restrict__ esrc = g_esrc[rel];
    int s = g_off[rel][gw];
    int e = g_off[rel][gw + 1];
    float4 a0 = make_float4(0.f, 0.f, 0.f, 0.f);
    float4 a1 = make_float4(0.f, 0.f, 0.f, 0.f);
    int j = s;
    for (; j + 3 < e; j += 4) {
        int s0 = __ldg(esrc + j), s1 = __ldg(esrc + j + 1);
        int s2 = __ldg(esrc + j + 2), s3 = __ldg(esrc + j + 3);
        uint2 u0 = __ldg((const uint2*)(h + (size_t)s0 * D) + lane);
        uint2 u1 = __ldg((const uint2*)(h + (size_t)s1 * D) + lane);
        uint2 u2 = __ldg((const uint2*)(h + (size_t)s2 * D) + lane);
        uint2 u3 = __ldg((const uint2*)(h + (size_t)s3 * D) + lane);
        float2 p;
        p = __half22float2(*(__half2*)&u0.x); a0.x += p.x; a0.y += p.y;
        p = __half22float2(*(__half2*)&u0.y); a0.z += p.x; a0.w += p.y;
        p = __half22float2(*(__half2*)&u1.x); a1.x += p.x; a1.y += p.y;
        p = __half22float2(*(__half2*)&u1.y); a1.z += p.x; a1.w += p.y;
        p = __half22float2(*(__half2*)&u2.x); a0.x += p.x; a0.y += p.y;
        p = __half22float2(*(__half2*)&u2.y); a0.z += p.x; a0.w += p.y;
        p = __half22float2(*(__half2*)&u3.x); a1.x += p.x; a1.y += p.y;
        p = __half22float2(*(__half2*)&u3.y); a1.z += p.x; a1.w += p.y;
    }
    for (; j < e; j++) {
        int s0 = __ldg(esrc + j);
        uint2 u0 = __ldg((const uint2*)(h + (size_t)s0 * D) + lane);
        float2 p;
        p = __half22float2(*(__half2*)&u0.x); a0.x += p.x; a0.y += p.y;
        p = __half22float2(*(__half2*)&u0.y); a0.z += p.x; a0.w += p.y;
    }
    float inv = (e > s) ? 1.f / (float)(e - s) : 0.f;
    __half2 lo = __floats2half2_rn((a0.x + a1.x) * inv, (a0.y + a1.y) * inv);
    __half2 hi = __floats2half2_rn((a0.z + a1.z) * inv, (a0.w + a1.w) * inv);
    uint2 m;
    m.x = *(uint32_t*)&lo;
    m.y = *(uint32_t*)&hi;
    ((uint2*)(out + (size_t)gw * D))[lane] = m;
}

// ---------------- fp16 mma GEMM (ldmatrix + cp.async) + LN -------------
__device__ __forceinline__ void mma16(float* c, uint32_t a0, uint32_t a1,
                                      uint32_t a2, uint32_t a3,
                                      uint32_t b0, uint32_t b1) {
    asm volatile(
        "mma.sync.aligned.m16n8k16.row.col.f32.f16.f16.f32 "
        "{%0,%1,%2,%3},{%4,%5,%6,%7},{%8,%9},{%0,%1,%2,%3};"
        : "+f"(c[0]), "+f"(c[1]), "+f"(c[2]), "+f"(c[3])
        : "r"(a0), "r"(a1), "r"(a2), "r"(a3), "r"(b0), "r"(b1));
}

__device__ __forceinline__ void ldsm4(uint32_t& r0, uint32_t& r1,
                                      uint32_t& r2, uint32_t& r3, uint32_t addr) {
    asm volatile("ldmatrix.sync.aligned.m8n8.x4.shared.b16 {%0,%1,%2,%3}, [%4];"
                 : "=r"(r0), "=r"(r1), "=r"(r2), "=r"(r3) : "r"(addr));
}

__device__ __forceinline__ void cpa16(uint32_t dst, const void* src, int pred) {
    asm volatile("cp.async.cg.shared.global [%0], [%1], 16, %2;"
                 :: "r"(dst), "l"(src), "r"(pred ? 16 : 0));
}

// C[M,128] = [A0|A1|A2][M,K] @ Wt^T; Wt layout [n][k]. BM=128, BN=128, BK=32.
__global__ __launch_bounds__(256)
void gemm_h_ln(const __half* __restrict__ A0, const __half* __restrict__ A1,
               const __half* __restrict__ A2, const __half* __restrict__ Wt,
               const float* __restrict__ bias, const float* __restrict__ gamma,
               const float* __restrict__ beta,
               __half* __restrict__ out16, float* __restrict__ out32,
               int M, int K, int relu) {
    __shared__ __half As[2][128 * TS];
    __shared__ __half Bs[2][128 * TS];
    int t = threadIdx.x, lane = t & 31, w = t >> 5;
    int bm = blockIdx.x * 128;
    int g = lane >> 2, c4 = lane & 3;
    int niter = K >> 5;

    uint32_t asb = (uint32_t)__cvta_generic_to_shared(&As[0][0]);
    uint32_t bsb = (uint32_t)__cvta_generic_to_shared(&Bs[0][0]);

    float acc[16][4];
#pragma unroll
    for (int tt = 0; tt < 16; tt++)
#pragma unroll
        for (int cc = 0; cc < 4; cc++) acc[tt][cc] = 0.f;

    int lrow = t >> 1;
    int lch = (t & 1) * 2;

    auto load_tile = [&](int it, int b) {
        int kt = it << 5;
        const __half* Aseg = (kt < 128) ? A0 : ((kt < 256) ? A1 : A2);
        int kcol = kt & 127;
        int gr = bm + lrow;
        int ok = gr < M;
        const __half* ap = Aseg + (size_t)(ok ? gr : 0) * D + kcol;
        uint32_t ad = asb + (uint32_t)(b * 128 * TS + lrow * TS) * 2;
        cpa16(ad + lch * 16, ap + lch * 8, ok);
        cpa16(ad + (lch + 1) * 16, ap + (lch + 1) * 8, ok);
        const __half* bp = Wt + (size_t)lrow * K + kt;
        uint32_t bd = bsb + (uint32_t)(b * 128 * TS + lrow * TS) * 2;
        cpa16(bd + lch * 16, bp + lch * 8, 1);
        cpa16(bd + (lch + 1) * 16, bp + (lch + 1) * 8, 1);
    };

    load_tile(0, 0);
    asm volatile("cp.async.commit_group;");

    for (int it = 0; it < niter; it++) {
        int buf = it & 1;
        if (it + 1 < niter) {
            load_tile(it + 1, buf ^ 1);
            asm volatile("cp.async.commit_group;");
            asm volatile("cp.async.wait_group 1;");
        } else {
            asm volatile("cp.async.wait_group 0;");
        }
        __syncthreads();

        uint32_t abase = asb + (uint32_t)(buf * 128 * TS) * 2;
        uint32_t bbase = bsb + (uint32_t)(buf * 128 * TS) * 2;
#pragma unroll
        for (int ks = 0; ks < 2; ks++) {
            uint32_t a0, a1, a2, a3;
            {
                int row = w * 16 + (lane & 15);
                int kc = ks * 16 + ((lane >> 4) << 3);
                ldsm4(a0, a1, a2, a3, abase + (uint32_t)(row * TS + kc) * 2);
            }
#pragma unroll
            for (int tp = 0; tp < 8; tp++) {
                uint32_t b0, b1, b2, b3;
                int n = tp * 16 + (((lane >> 4) & 1) << 3) + (lane & 7);
                int kc = ks * 16 + (((lane >> 3) & 1) << 3);
                ldsm4(b0, b1, b2, b3, bbase + (uint32_t)(n * TS + kc) * 2);
                mma16(acc[2 * tp], a0, a1, a2, a3, b0, b1);
                mma16(acc[2 * tp + 1], a0, a1, a2, a3, b2, b3);
            }
        }
        __syncthreads();
    }

    int rowa = bm + w * 16 + g;
    int rowb = rowa + 8;
    float s0 = 0.f, q0 = 0.f, s1 = 0.f, q1 = 0.f;
#pragma unroll
    for (int tt = 0; tt < 16; tt++) {
        int col = tt * 8 + c4 * 2;
        float2 bf = *(const float2*)(bias + col);
        float v0 = acc[tt][0] + bf.x, v1 = acc[tt][1] + bf.y;
        float v2 = acc[tt][2] + bf.x, v3 = acc[tt][3] + bf.y;
        acc[tt][0] = v0; acc[tt][1] = v1; acc[tt][2] = v2; acc[tt][3] = v3;
        s0 += v0 + v1; q0 += v0 * v0 + v1 * v1;
        s1 += v2 + v3; q1 += v2 * v2 + v3 * v3;
    }
#pragma unroll
    for (int o = 1; o < 4; o <<= 1) {
        s0 += __shfl_xor_sync(0xffffffffu, s0, o);
        q0 += __shfl_xor_sync(0xffffffffu, q0, o);
        s1 += __shfl_xor_sync(0xffffffffu, s1, o);
        q1 += __shfl_xor_sync(0xffffffffu, q1, o);
    }
    float m0 = s0 * (1.f / 128.f), m1 = s1 * (1.f / 128.f);
    float rs0 = rsqrtf(q0 * (1.f / 128.f) - m0 * m0 + LN_EPS);
    float rs1 = rsqrtf(q1 * (1.f / 128.f) - m1 * m1 + LN_EPS);
#pragma unroll
    for (int tt = 0; tt < 16; tt++) {
        int col = tt * 8 + c4 * 2;
        float2 ga = *(const float2*)(gamma + col);
        float2 be = *(const float2*)(beta + col);
        float o0 = (acc[tt][0] - m0) * rs0 * ga.x + be.x;
        float o1 = (acc[tt][1] - m0) * rs0 * ga.y + be.y;
        float o2 = (acc[tt][2] - m1) * rs1 * ga.x + be.x;
        float o3 = (acc[tt][3] - m1) * rs1 * ga.y + be.y;
        if (relu) {
            o0 = fmaxf(o0, 0.f); o1 = fmaxf(o1, 0.f);
            o2 = fmaxf(o2, 0.f); o3 = fmaxf(o3, 0.f);
        }
        if (out32) {
            if (rowa < M) *(float2*)(out32 + (size_t)rowa * D + col) = make_float2(o0, o1);
            if (rowb < M) *(float2*)(out32 + (size_t)rowb * D + col) = make_float2(o2, o3);
        } else {
            if (rowa < M) *(__half2*)(out16 + (size_t)rowa * D + col) = __floats2half2_rn(o0, o1);
            if (rowb < M) *(__half2*)(out16 + (size_t)rowb * D + col) = __floats2half2_rn(o2, o3);
        }
    }
}

// ---------------- launch ------------------------------------------------
extern "C" void kernel_launch(void* const* d_in, const int* in_sizes, int n_in,
                              void* d_out, int out_size) {
    const float* x_c   = (const float*)d_in[0];
    const float* x_pc  = (const float*)d_in[1];
    const int*   src0  = (const int*)d_in[2];
    const int*   dst0  = (const int*)d_in[3];
    const int*   src1  = (const int*)d_in[4];
    const int*   dst1  = (const int*)d_in[5];
    const float* Wself = (const float*)d_in[6];
    const float* Wneigh= (const float*)d_in[7];
    const float* bneigh= (const float*)d_in[8];
    const float* linW  = (const float*)d_in[9];
    const float* linb  = (const float*)d_in[10];
    const float* gamma = (const float*)d_in[11];
    const float* beta  = (const float*)d_in[12];
    float* out = (float*)d_out;

    __half *p_h16, *p_pc16, *p_m16, *p_w16, *p_lw16;
    float *p_bc;
    void *p_deg;
    cudaGetSymbolAddress((void**)&p_h16,  g_h16);
    cudaGetSymbolAddress((void**)&p_pc16, g_pc16);
    cudaGetSymbolAddress((void**)&p_m16,  g_m16);
    cudaGetSymbolAddress((void**)&p_w16,  g_w16);
    cudaGetSymbolAddress((void**)&p_lw16, g_lw16);
    cudaGetSymbolAddress((void**)&p_bc,   g_bcomb);
    cudaGetSymbolAddress(&p_deg, g_deg);
    __half* p_m0 = p_m16;
    __half* p_m1 = p_m16 + (size_t)N_C * D;

    static cudaStream_t s2;
    static cudaEvent_t ev_fork, ev_side, ev_join;
    static int init_done = 0;
    if (!init_done) {
        cudaStreamCreateWithFlags(&s2, cudaStreamNonBlocking);
        cudaEventCreateWithFlags(&ev_fork, cudaEventDisableTiming);
        cudaEventCreateWithFlags(&ev_side, cudaEventDisableTiming);
        cudaEventCreateWithFlags(&ev_join, cudaEventDisableTiming);
        init_done = 1;
    }

    // fork side stream from the (capturing) main stream
    cudaEventRecord(ev_fork, 0);
    cudaStreamWaitEvent(s2, ev_fork, 0);

    // side stream: weight prep + fp16 conversion (independent of CSR build)
    prep_weights<<<(NL * KCOMB * D + 255) / 256, 256, 0, s2>>>(Wself, Wneigh, bneigh, linW);
    cvt_all<<<(NC4 + NPC4 + 255) / 256, 256, 0, s2>>>(
        (const float4*)x_c, (const float4*)x_pc, (uint2*)p_h16, (uint2*)p_pc16);
    cudaEventRecord(ev_side, s2);

    // main stream: CSR build (concurrent with side)
    cudaMemsetAsync(p_deg, 0, 2 * N_C * sizeof(int));
    hist_kernel<<<(2 * NE + 255) / 256, 256>>>(dst0, dst1);
    scan_partial<<<dim3(NCHUNK, 2), 1024>>>();
    add_base2<<<dim3(NCHUNK, 2), 1024>>>();
    scatter_kernel<<<(2 * NE + 255) / 256, 256>>>(src0, dst0, src1, dst1);

    // main needs h16 + combined weights before the layer loop
    cudaStreamWaitEvent(0, ev_side, 0);

    for (int l = 0; l < NL; l++) {
        int last = (l == NL - 1);
        // main: aggregation (64-thread blocks: finest slot retirement) + GEMM
        agg_kernel<<<dim3((N_C + 1) / 2, 2), 64>>>(p_h16);
        gemm_h_ln<<<(N_C + 127) / 128, 256>>>(
            p_h16, p_m0, p_m1,
            p_w16 + (size_t)l * D * KCOMB, p_bc + (size_t)l * D,
            gamma + (size_t)l * D, beta + (size_t)l * D,
            p_h16, last ? out + (size_t)N_PC * D : nullptr,
            N_C, KCOMB, last ? 0 : 1);
        // side: PC linear chain (independent of compound path)
        gemm_h_ln<<<(N_PC + 127) / 128, 256, 0, s2>>>(
            p_pc16, p_pc16, p_pc16,
            p_lw16 + (size_t)l * D * D, linb + (size_t)l * D,
            gamma + (size_t)l * D, beta + (size_t)l * D,
            p_pc16, last ? out : nullptr,
            N_PC, D, last ? 0 : 1);
    }

    // join side stream back into main before capture ends
    cudaEventRecord(ev_join, s2);
    cudaStreamWaitEvent(0, ev_join, 0);
}

// round 17
// speedup vs baseline: 1.0124x; 1.0124x over previous
#include <cuda_runtime.h>
#include <cuda_fp16.h>
#include <cstdint>

#define N_C   100000
#define N_PC  10000
#define NE    1000000
#define D     128
#define NL    3
#define KCOMB 384
#define LN_EPS 1e-5f
#define NCHUNK 98          // ceil(N_C/1024)
#define TS 40              // fp16 elems per smem tile row (32 + 8 pad)
#define NC4  (N_C * D / 4)
#define NPC4 (N_PC * D / 4)

// ---------------- device scratch (static, no allocation) ----------------
static __device__ __align__(16) __half g_h16[N_C * D];
static __device__ __align__(16) __half g_pc16[N_PC * D];
static __device__ __align__(16) __half g_m16[2][N_C * D];
static __device__ __align__(16) __half g_w16[NL * D * KCOMB];   // [l][n][k]
static __device__ __align__(16) __half g_lw16[NL * D * D];      // [l][n][k]
static __device__ int   g_deg[2][N_C];
static __device__ int   g_off[2][N_C + 1];
static __device__ int   g_cur[2][N_C];
static __device__ int   g_esrc[2][NE];
static __device__ int   g_psum[2][NCHUNK + 1];
static __device__ float g_bcomb[NL][D];

// ---------------- input conversion fp32 -> fp16 (both tensors) ----------
__global__ void cvt_all(const float4* __restrict__ xc, const float4* __restrict__ xpc,
                        uint2* __restrict__ yc, uint2* __restrict__ ypc) {
    int i = blockIdx.x * blockDim.x + threadIdx.x;
    if (i < NC4) {
        float4 v = xc[i];
        __half2 lo = __floats2half2_rn(v.x, v.y);
        __half2 hi = __floats2half2_rn(v.z, v.w);
        yc[i] = make_uint2(*(uint32_t*)&lo, *(uint32_t*)&hi);
    } else if (i < NC4 + NPC4) {
        float4 v = xpc[i - NC4];
        __half2 lo = __floats2half2_rn(v.x, v.y);
        __half2 hi = __floats2half2_rn(v.z, v.w);
        ypc[i - NC4] = make_uint2(*(uint32_t*)&lo, *(uint32_t*)&hi);
    }
}

// ---------------- weight prep (combined, transposed, fp16) --------------
__global__ void prep_weights(const float* __restrict__ Wself,
                             const float* __restrict__ Wneigh,
                             const float* __restrict__ bneigh,
                             const float* __restrict__ linW) {
    int idx = blockIdx.x * blockDim.x + threadIdx.x;
    int total = NL * KCOMB * D;
    if (idx < total) {
        int l = idx / (KCOMB * D);
        int rem = idx - l * (KCOMB * D);
        int k = rem / D;
        int n = rem - k * D;
        float v;
        if (k < D) {
            v = Wself[((l * 2 + 0) * D + k) * D + n] +
                Wself[((l * 2 + 1) * D + k) * D + n];
        } else if (k < 2 * D) {
            v = Wneigh[((l * 2 + 0) * D + (k - D)) * D + n];
        } else {
            v = Wneigh[((l * 2 + 1) * D + (k - 2 * D)) * D + n];
        }
        g_w16[(l * D + n) * KCOMB + k] = __float2half_rn(v);
    }
    if (idx < NL * D * D) {
        int l = idx / (D * D);
        int rem = idx - l * (D * D);
        int k = rem / D;
        int n = rem - k * D;
        g_lw16[(l * D + n) * D + k] = __float2half_rn(linW[idx]);
    }
    if (idx < NL * D) {
        int l = idx / D, n = idx - l * D;
        g_bcomb[l][n] = bneigh[(l * 2 + 0) * D + n] + bneigh[(l * 2 + 1) * D + n];
    }
}

// ---------------- CSR build --------------------------------------------
__global__ void hist_kernel(const int* __restrict__ dst0,
                            const int* __restrict__ dst1) {
    int idx = blockIdx.x * blockDim.x + threadIdx.x;
    if (idx < NE) {
        atomicAdd(&g_deg[0][dst0[idx]], 1);
    } else if (idx < 2 * NE) {
        atomicAdd(&g_deg[1][dst1[idx - NE]], 1);
    }
}

__global__ void scan_partial() {
    int r = blockIdx.y;
    int i = blockIdx.x * 1024 + threadIdx.x;
    int lane = threadIdx.x & 31, wid = threadIdx.x >> 5;
    int v = (i < N_C) ? g_deg[r][i] : 0;
    int x = v;
#pragma unroll
    for (int o = 1; o < 32; o <<= 1) {
        int y = __shfl_up_sync(0xffffffffu, x, o);
        if (lane >= o) x += y;
    }
    __shared__ int ws[32];
    if (lane == 31) ws[wid] = x;
    __syncthreads();
    if (wid == 0) {
        int y = ws[lane];
#pragma unroll
        for (int o = 1; o < 32; o <<= 1) {
            int z = __shfl_up_sync(0xffffffffu, y, o);
            if (lane >= o) y += z;
        }
        ws[lane] = y;
    }
    __syncthreads();
    int base = wid ? ws[wid - 1] : 0;
    if (i < N_C) g_off[r][i] = base + x - v;
    if (threadIdx.x == 1023) g_psum[r][blockIdx.x] = base + x;
}

// add_base with in-block parallel reduction of chunk totals
__global__ void add_base2() {
    int r = blockIdx.y;
    __shared__ int sarr[128];
    int tid = threadIdx.x;
    if (tid < 128) sarr[tid] = (tid < blockIdx.x && tid < NCHUNK) ? g_psum[r][tid] : 0;
    __syncthreads();
#pragma unroll
    for (int o = 64; o; o >>= 1) {
        if (tid < o) sarr[tid] += sarr[tid + o];
        __syncthreads();
    }
    int base = sarr[0];
    int i = blockIdx.x * 1024 + tid;
    if (i < N_C) {
        int o = g_off[r][i] + base;
        g_off[r][i] = o;
        g_cur[r][i] = o;
    }
    if (tid == 0 && blockIdx.x == NCHUNK - 1)
        g_off[r][N_C] = base + g_psum[r][NCHUNK - 1];
}

__global__ void scatter_kernel(const int* __restrict__ src0,
                               const int* __restrict__ dst0,
                               const int* __restrict__ src1,
                               const int* __restrict__ dst1) {
    int idx = blockIdx.x * blockDim.x + threadIdx.x;
    if (idx < NE) {
        int d = dst0[idx];
        int p = atomicAdd(&g_cur[0][d], 1);
        g_esrc[0][p] = src0[idx];
    } else if (idx < 2 * NE) {
        int e = idx - NE;
        int d = dst1[e];
        int p = atomicAdd(&g_cur[1][d], 1);
        g_esrc[1][p] = src1[e];
    }
}

// ------ mean aggregation: warp/dst, 4-deep prefetch; 128-thread blocks --
__global__ void agg_kernel(const __half* __restrict__ h) {
    int rel = blockIdx.y;
    int gw = (blockIdx.x * blockDim.x + threadIdx.x) >> 5;
    int lane = threadIdx.x & 31;
    if (gw >= N_C) return;
    __half* __restrict__ out = g_m16[rel];
    const int* __restrict__ esrc = g_esrc[rel];
    int s = g_off[rel][gw];
    int e = g_off[rel][gw + 1];
    float4 a0 = make_float4(0.f, 0.f, 0.f, 0.f);
    float4 a1 = make_float4(0.f, 0.f, 0.f, 0.f);
    int j = s;
    for (; j + 3 < e; j += 4) {
        int s0 = __ldg(esrc + j), s1 = __ldg(esrc + j + 1);
        int s2 = __ldg(esrc + j + 2), s3 = __ldg(esrc + j + 3);
        uint2 u0 = __ldg((const uint2*)(h + (size_t)s0 * D) + lane);
        uint2 u1 = __ldg((const uint2*)(h + (size_t)s1 * D) + lane);
        uint2 u2 = __ldg((const uint2*)(h + (size_t)s2 * D) + lane);
        uint2 u3 = __ldg((const uint2*)(h + (size_t)s3 * D) + lane);
        float2 p;
        p = __half22float2(*(__half2*)&u0.x); a0.x += p.x; a0.y += p.y;
        p = __half22float2(*(__half2*)&u0.y); a0.z += p.x; a0.w += p.y;
        p = __half22float2(*(__half2*)&u1.x); a1.x += p.x; a1.y += p.y;
        p = __half22float2(*(__half2*)&u1.y); a1.z += p.x; a1.w += p.y;
        p = __half22float2(*(__half2*)&u2.x); a0.x += p.x; a0.y += p.y;
        p = __half22float2(*(__half2*)&u2.y); a0.z += p.x; a0.w += p.y;
        p = __half22float2(*(__half2*)&u3.x); a1.x += p.x; a1.y += p.y;
        p = __half22float2(*(__half2*)&u3.y); a1.z += p.x; a1.w += p.y;
    }
    for (; j < e; j++) {
        int s0 = __ldg(esrc + j);
        uint2 u0 = __ldg((const uint2*)(h + (size_t)s0 * D) + lane);
        float2 p;
        p = __half22float2(*(__half2*)&u0.x); a0.x += p.x; a0.y += p.y;
        p = __half22float2(*(__half2*)&u0.y); a0.z += p.x; a0.w += p.y;
    }
    float inv = (e > s) ? 1.f / (float)(e - s) : 0.f;
    __half2 lo = __floats2half2_rn((a0.x + a1.x) * inv, (a0.y + a1.y) * inv);
    __half2 hi = __floats2half2_rn((a0.z + a1.z) * inv, (a0.w + a1.w) * inv);
    uint2 m;
    m.x = *(uint32_t*)&lo;
    m.y = *(uint32_t*)&hi;
    ((uint2*)(out + (size_t)gw * D))[lane] = m;
}

// ---------------- fp16 mma GEMM (ldmatrix + cp.async) + LN -------------
__device__ __forceinline__ void mma16(float* c, uint32_t a0, uint32_t a1,
                                      uint32_t a2, uint32_t a3,
                                      uint32_t b0, uint32_t b1) {
    asm volatile(
        "mma.sync.aligned.m16n8k16.row.col.f32.f16.f16.f32 "
        "{%0,%1,%2,%3},{%4,%5,%6,%7},{%8,%9},{%0,%1,%2,%3};"
        : "+f"(c[0]), "+f"(c[1]), "+f"(c[2]), "+f"(c[3])
        : "r"(a0), "r"(a1), "r"(a2), "r"(a3), "r"(b0), "r"(b1));
}

__device__ __forceinline__ void ldsm4(uint32_t& r0, uint32_t& r1,
                                      uint32_t& r2, uint32_t& r3, uint32_t addr) {
    asm volatile("ldmatrix.sync.aligned.m8n8.x4.shared.b16 {%0,%1,%2,%3}, [%4];"
                 : "=r"(r0), "=r"(r1), "=r"(r2), "=r"(r3) : "r"(addr));
}

__device__ __forceinline__ void cpa16(uint32_t dst, const void* src, int pred) {
    asm volatile("cp.async.cg.shared.global [%0], [%1], 16, %2;"
                 :: "r"(dst), "l"(src), "r"(pred ? 16 : 0));
}

// C[M,128] = [A0|A1|A2][M,K] @ Wt^T; Wt layout [n][k]. BM=128, BN=128, BK=32.
__global__ __launch_bounds__(256)
void gemm_h_ln(const __half* __restrict__ A0, const __half* __restrict__ A1,
               const __half* __restrict__ A2, const __half* __restrict__ Wt,
               const float* __restrict__ bias, const float* __restrict__ gamma,
               const float* __restrict__ beta,
               __half* __restrict__ out16, float* __restrict__ out32,
               int M, int K, int relu) {
    __shared__ __half As[2][128 * TS];
    __shared__ __half Bs[2][128 * TS];
    int t = threadIdx.x, lane = t & 31, w = t >> 5;
    int bm = blockIdx.x * 128;
    int g = lane >> 2, c4 = lane & 3;
    int niter = K >> 5;

    uint32_t asb = (uint32_t)__cvta_generic_to_shared(&As[0][0]);
    uint32_t bsb = (uint32_t)__cvta_generic_to_shared(&Bs[0][0]);

    float acc[16][4];
#pragma unroll
    for (int tt = 0; tt < 16; tt++)
#pragma unroll
        for (int cc = 0; cc < 4; cc++) acc[tt][cc] = 0.f;

    int lrow = t >> 1;
    int lch = (t & 1) * 2;

    auto load_tile = [&](int it, int b) {
        int kt = it << 5;
        const __half* Aseg = (kt < 128) ? A0 : ((kt < 256) ? A1 : A2);
        int kcol = kt & 127;
        int gr = bm + lrow;
        int ok = gr < M;
        const __half* ap = Aseg + (size_t)(ok ? gr : 0) * D + kcol;
        uint32_t ad = asb + (uint32_t)(b * 128 * TS + lrow * TS) * 2;
        cpa16(ad + lch * 16, ap + lch * 8, ok);
        cpa16(ad + (lch + 1) * 16, ap + (lch + 1) * 8, ok);
        const __half* bp = Wt + (size_t)lrow * K + kt;
        uint32_t bd = bsb + (uint32_t)(b * 128 * TS + lrow * TS) * 2;
        cpa16(bd + lch * 16, bp + lch * 8, 1);
        cpa16(bd + (lch + 1) * 16, bp + (lch + 1) * 8, 1);
    };

    load_tile(0, 0);
    asm volatile("cp.async.commit_group;");

    for (int it = 0; it < niter; it++) {
        int buf = it & 1;
        if (it + 1 < niter) {
            load_tile(it + 1, buf ^ 1);
            asm volatile("cp.async.commit_group;");
            asm volatile("cp.async.wait_group 1;");
        } else {
            asm volatile("cp.async.wait_group 0;");
        }
        __syncthreads();

        uint32_t abase = asb + (uint32_t)(buf * 128 * TS) * 2;
        uint32_t bbase = bsb + (uint32_t)(buf * 128 * TS) * 2;
#pragma unroll
        for (int ks = 0; ks < 2; ks++) {
            uint32_t a0, a1, a2, a3;
            {
                int row = w * 16 + (lane & 15);
                int kc = ks * 16 + ((lane >> 4) << 3);
                ldsm4(a0, a1, a2, a3, abase + (uint32_t)(row * TS + kc) * 2);
            }
#pragma unroll
            for (int tp = 0; tp < 8; tp++) {
                uint32_t b0, b1, b2, b3;
                int n = tp * 16 + (((lane >> 4) & 1) << 3) + (lane & 7);
                int kc = ks * 16 + (((lane >> 3) & 1) << 3);
                ldsm4(b0, b1, b2, b3, bbase + (uint32_t)(n * TS + kc) * 2);
                mma16(acc[2 * tp], a0, a1, a2, a3, b0, b1);
                mma16(acc[2 * tp + 1], a0, a1, a2, a3, b2, b3);
            }
        }
        __syncthreads();
    }

    int rowa = bm + w * 16 + g;
    int rowb = rowa + 8;
    float s0 = 0.f, q0 = 0.f, s1 = 0.f, q1 = 0.f;
#pragma unroll
    for (int tt = 0; tt < 16; tt++) {
        int col = tt * 8 + c4 * 2;
        float2 bf = *(const float2*)(bias + col);
        float v0 = acc[tt][0] + bf.x, v1 = acc[tt][1] + bf.y;
        float v2 = acc[tt][2] + bf.x, v3 = acc[tt][3] + bf.y;
        acc[tt][0] = v0; acc[tt][1] = v1; acc[tt][2] = v2; acc[tt][3] = v3;
        s0 += v0 + v1; q0 += v0 * v0 + v1 * v1;
        s1 += v2 + v3; q1 += v2 * v2 + v3 * v3;
    }
#pragma unroll
    for (int o = 1; o < 4; o <<= 1) {
        s0 += __shfl_xor_sync(0xffffffffu, s0, o);
        q0 += __shfl_xor_sync(0xffffffffu, q0, o);
        s1 += __shfl_xor_sync(0xffffffffu, s1, o);
        q1 += __shfl_xor_sync(0xffffffffu, q1, o);
    }
    float m0 = s0 * (1.f / 128.f), m1 = s1 * (1.f / 128.f);
    float rs0 = rsqrtf(q0 * (1.f / 128.f) - m0 * m0 + LN_EPS);
    float rs1 = rsqrtf(q1 * (1.f / 128.f) - m1 * m1 + LN_EPS);
#pragma unroll
    for (int tt = 0; tt < 16; tt++) {
        int col = tt * 8 + c4 * 2;
        float2 ga = *(const float2*)(gamma + col);
        float2 be = *(const float2*)(beta + col);
        float o0 = (acc[tt][0] - m0) * rs0 * ga.x + be.x;
        float o1 = (acc[tt][1] - m0) * rs0 * ga.y + be.y;
        float o2 = (acc[tt][2] - m1) * rs1 * ga.x + be.x;
        float o3 = (acc[tt][3] - m1) * rs1 * ga.y + be.y;
        if (relu) {
            o0 = fmaxf(o0, 0.f); o1 = fmaxf(o1, 0.f);
            o2 = fmaxf(o2, 0.f); o3 = fmaxf(o3, 0.f);
        }
        if (out32) {
            if (rowa < M) *(float2*)(out32 + (size_t)rowa * D + col) = make_float2(o0, o1);
            if (rowb < M) *(float2*)(out32 + (size_t)rowb * D + col) = make_float2(o2, o3);
        } else {
            if (rowa < M) *(__half2*)(out16 + (size_t)rowa * D + col) = __floats2half2_rn(o0, o1);
            if (rowb < M) *(__half2*)(out16 + (size_t)rowb * D + col) = __floats2half2_rn(o2, o3);
        }
    }
}

// ---------------- launch ------------------------------------------------
extern "C" void kernel_launch(void* const* d_in, const int* in_sizes, int n_in,
                              void* d_out, int out_size) {
    const float* x_c   = (const float*)d_in[0];
    const float* x_pc  = (const float*)d_in[1];
    const int*   src0  = (const int*)d_in[2];
    const int*   dst0  = (const int*)d_in[3];
    const int*   src1  = (const int*)d_in[4];
    const int*   dst1  = (const int*)d_in[5];
    const float* Wself = (const float*)d_in[6];
    const float* Wneigh= (const float*)d_in[7];
    const float* bneigh= (const float*)d_in[8];
    const float* linW  = (const float*)d_in[9];
    const float* linb  = (const float*)d_in[10];
    const float* gamma = (const float*)d_in[11];
    const float* beta  = (const float*)d_in[12];
    float* out = (float*)d_out;

    __half *p_h16, *p_pc16, *p_m16, *p_w16, *p_lw16;
    float *p_bc;
    void *p_deg;
    cudaGetSymbolAddress((void**)&p_h16,  g_h16);
    cudaGetSymbolAddress((void**)&p_pc16, g_pc16);
    cudaGetSymbolAddress((void**)&p_m16,  g_m16);
    cudaGetSymbolAddress((void**)&p_w16,  g_w16);
    cudaGetSymbolAddress((void**)&p_lw16, g_lw16);
    cudaGetSymbolAddress((void**)&p_bc,   g_bcomb);
    cudaGetSymbolAddress(&p_deg, g_deg);
    __half* p_m0 = p_m16;
    __half* p_m1 = p_m16 + (size_t)N_C * D;

    static cudaStream_t s2;
    static cudaEvent_t ev_fork, ev_side, ev_join;
    static int init_done = 0;
    if (!init_done) {
        cudaStreamCreateWithFlags(&s2, cudaStreamNonBlocking);
        cudaEventCreateWithFlags(&ev_fork, cudaEventDisableTiming);
        cudaEventCreateWithFlags(&ev_side, cudaEventDisableTiming);
        cudaEventCreateWithFlags(&ev_join, cudaEventDisableTiming);
        init_done = 1;
    }

    // fork side stream from the (capturing) main stream
    cudaEventRecord(ev_fork, 0);
    cudaStreamWaitEvent(s2, ev_fork, 0);

    // side stream: weight prep + fp16 conversion (independent of CSR build)
    prep_weights<<<(NL * KCOMB * D + 255) / 256, 256, 0, s2>>>(Wself, Wneigh, bneigh, linW);
    cvt_all<<<(NC4 + NPC4 + 255) / 256, 256, 0, s2>>>(
        (const float4*)x_c, (const float4*)x_pc, (uint2*)p_h16, (uint2*)p_pc16);
    cudaEventRecord(ev_side, s2);

    // main stream: CSR build (concurrent with side)
    cudaMemsetAsync(p_deg, 0, 2 * N_C * sizeof(int));
    hist_kernel<<<(2 * NE + 255) / 256, 256>>>(dst0, dst1);
    scan_partial<<<dim3(NCHUNK, 2), 1024>>>();
    add_base2<<<dim3(NCHUNK, 2), 1024>>>();
    scatter_kernel<<<(2 * NE + 255) / 256, 256>>>(src0, dst0, src1, dst1);

    // main needs h16 + combined weights before the layer loop
    cudaStreamWaitEvent(0, ev_side, 0);

    for (int l = 0; l < NL; l++) {
        int last = (l == NL - 1);
        // main: aggregation (128-thread blocks: finer slot retirement) + GEMM
        agg_kernel<<<dim3((N_C + 3) / 4, 2), 128>>>(p_h16);
        gemm_h_ln<<<(N_C + 127) / 128, 256>>>(
            p_h16, p_m0, p_m1,
            p_w16 + (size_t)l * D * KCOMB, p_bc + (size_t)l * D,
            gamma + (size_t)l * D, beta + (size_t)l * D,
            p_h16, last ? out + (size_t)N_PC * D : nullptr,
            N_C, KCOMB, last ? 0 : 1);
        // side: PC linear chain (independent of compound path)
        gemm_h_ln<<<(N_PC + 127) / 128, 256, 0, s2>>>(
            p_pc16, p_pc16, p_pc16,
            p_lw16 + (size_t)l * D * D, linb + (size_t)l * D,
            gamma + (size_t)l * D, beta + (size_t)l * D,
            p_pc16, last ? out : nullptr,
            N_PC, D, last ? 0 : 1);
    }

    // join side stream back into main before capture ends
    cudaEventRecord(ev_join, s2);
    cudaStreamWaitEvent(0, ev_join, 0);
}